// round 13
// baseline (speedup 1.0000x reference)
#include <cuda_runtime.h>
#include <cstdint>

#define BATCH 256
#define L 4096
#define H 128
#define RING 16

// ---------- packed f32x2 helpers (Blackwell sm_103a) ----------
__device__ __forceinline__ uint64_t pack2f(float a, float b) {
    uint64_t r; asm("mov.b64 %0, {%1, %2};" : "=l"(r) : "f"(a), "f"(b)); return r;
}
__device__ __forceinline__ float hsum2(uint64_t v) {
    float a, b; asm("mov.b64 {%0, %1}, %2;" : "=f"(a), "=f"(b) : "l"(v)); return a + b;
}
__device__ __forceinline__ uint64_t ffma2(uint64_t a, uint64_t b, uint64_t c) {
    uint64_t d; asm("fma.rn.f32x2 %0, %1, %2, %3;" : "=l"(d) : "l"(a), "l"(b), "l"(c)); return d;
}
__device__ __forceinline__ uint64_t fadd2(uint64_t a, uint64_t b) {
    uint64_t d; asm("add.rn.f32x2 %0, %1, %2;" : "=l"(d) : "l"(a), "l"(b)); return d;
}
__device__ __forceinline__ float elu1(float x) {
    return fmaxf(x, 0.f) + (__expf(fminf(x, 0.f)) - 1.f);
}
__device__ __forceinline__ uint32_t ctarank() {
    uint32_t r; asm("mov.u32 %0, %%cluster_ctarank;" : "=r"(r)); return r;
}
template <typename T>
__device__ __forceinline__ T* mapa_ptr(T* p, uint32_t rank) {
    uint64_t r;
    asm("mapa.u64 %0, %1, %2;" : "=l"(r) : "l"((uint64_t)p), "r"(rank));
    return (T*)r;
}
__device__ __forceinline__ void st_release_cluster(unsigned* p, unsigned v) {
    asm volatile("st.release.cluster.u32 [%0], %1;" :: "l"(p), "r"(v) : "memory");
}
__device__ __forceinline__ unsigned ld_acquire_cluster(const unsigned* p) {
    unsigned v;
    asm volatile("ld.acquire.cluster.u32 %0, [%1];" : "=r"(v) : "l"(p) : "memory");
    return v;
}
#define CLUSTER_SYNC() do { \
    asm volatile("barrier.cluster.arrive.aligned;" ::: "memory"); \
    asm volatile("barrier.cluster.wait.aligned;"   ::: "memory"); \
} while (0)

// Cluster (2,1,1): rank 0 = layer-1 producer, rank 1 = layer-2 consumer + head.
// Same proven R12 skeleton; synchronization tax removed:
//  - consumer: ALL threads poll the local flag (no tid0->barrier rebroadcast)
//  - producer: flag published every 2 steps (after the step barrier that
//    already orders all threads' DSMEM stores)
//  - consumer: credit published every 8 steps; producer gate hoisted before
//    the matvec so the (rare) refresh hides under compute.
// Ring-safety: producer allows slot t only if t <= cred+14 with cred <= true
// consumed count => never overwrites an unread slot (RING=16). Deadlock-free:
// consumer publishes at t%8==7 incl. t=L-1; producer's last gate needs 4081.
__global__ void __launch_bounds__(256, 2) __cluster_dims__(2, 1, 1)
rnn_cluster_kernel(const int* __restrict__ x,
                   const float* __restrict__ W_in,
                   const float* __restrict__ W_c,
                   const float* __restrict__ W_out,
                   const float* __restrict__ b_out,
                   float* __restrict__ out)
{
    __shared__ __align__(16) float sh_h[2][2 * H];        // h1 (rank0) / h2 (rank1) ping-pong
    __shared__ __align__(16) float sh_ring[RING][2 * H];  // rank1: h1 ring (16 KB)
    __shared__ __align__(16) float sh_prod[RING][2 * H];  // rank1: head ring (16 KB)
    __shared__ __align__(16) float sh_r[3 * H];           // rank0 only
    __shared__ uint8_t sh_x[2 * L];                       // both (8 KB)
    __shared__ float sh_acc[8][2];
    __shared__ unsigned sh_flag;     // rank1: published step count (written by rank0)
    __shared__ unsigned sh_credit;   // rank0: consumed step count (written by rank1)

    const int tid  = threadIdx.x;
    const int warp = tid >> 5;
    const int lane = tid & 31;
    const int i    = tid >> 1;
    const int s    = tid & 1;
    const uint32_t rank = ctarank();
    const int b0   = (blockIdx.x >> 1) * 2;

    // ---- common staging ----
    const int* xg = x + (size_t)b0 * L;
    #pragma unroll 4
    for (int idx = tid; idx < 2 * L; idx += 256) sh_x[idx] = (uint8_t)xg[idx];
    if (tid < 2 * H) sh_h[0][tid] = 0.f;
    if (tid == 0) { sh_flag = 0u; sh_credit = 0u; }

    const float* Wl = W_c + (rank ? H * H : 0);
    uint64_t w[32];
    #pragma unroll
    for (int j = 0; j < 16; ++j) {
        const int k0 = 8 * j + 4 * s;
        w[2*j]   = pack2f(Wl[(k0+0)*H + i], Wl[(k0+1)*H + i]);
        w[2*j+1] = pack2f(Wl[(k0+2)*H + i], Wl[(k0+3)*H + i]);
    }
    if (rank == 0) {
        if (tid < 2 * H) sh_r[tid] = elu1(W_in[tid]);
        if (tid < H)     sh_r[2 * H + tid] = 0.f;
    }
    __syncthreads();
    CLUSTER_SYNC();   // flags/rings initialized cluster-wide before any traffic

    if (rank == 0) {
        // ===================== PRODUCER: layer-1 scan =====================
        float*    peer_ring = mapa_ptr(&sh_ring[0][0], 1u);
        unsigned* peer_flag = mapa_ptr(&sh_flag, 1u);
        unsigned  cred = 0u;

        for (int t = 0; t < L; ++t) {
            // gate slot t (stay <= 14 ahead of last-known consumed count);
            // hoisted before the matvec so refreshes hide under compute
            if (tid == 0 && (unsigned)t > cred + (RING - 2)) {
                do { cred = ld_acquire_cluster(&sh_credit); }
                while ((unsigned)t > cred + (RING - 2));
            }

            const int p = t & 1;
            const float* hr = &sh_h[p][0];
            const int   prev = t ? (int)sh_x[s * L + t - 1] : 2;
            const float rv   = sh_r[prev * H + i];

            uint64_t a00 = 0, a01 = 0, a10 = 0, a11 = 0;
            #pragma unroll
            for (int j = 0; j < 16; ++j) {
                const int o = 8 * j + 4 * s;
                const ulonglong2 h0 = *(const ulonglong2*)(hr + o);
                const ulonglong2 h1 = *(const ulonglong2*)(hr + H + o);
                a00 = ffma2(w[2*j],   h0.x, a00);
                a01 = ffma2(w[2*j+1], h0.y, a01);
                a10 = ffma2(w[2*j],   h1.x, a10);
                a11 = ffma2(w[2*j+1], h1.y, a11);
            }
            float p0 = hsum2(fadd2(a00, a01));
            float p1 = hsum2(fadd2(a10, a11));
            p0 += __shfl_xor_sync(0xffffffffu, p0, 1);
            p1 += __shfl_xor_sync(0xffffffffu, p1, 1);

            const float h1n = elu1(s ? p1 : p0) + rv;
            sh_h[p ^ 1][s * H + i] = h1n;                          // own recurrence
            peer_ring[(t & (RING - 1)) * 2 * H + s * H + i] = h1n; // DSMEM store

            __syncthreads();   // orders ALL threads' stores (steps <= t)
            // publish every 2 steps; barrier above makes all stores visible,
            // release store then publishes them cluster-wide
            if ((t & 1) && tid == 0)
                st_release_cluster(peer_flag, (unsigned)(t + 1));
        }
    } else {
        // ============== CONSUMER: layer-2 scan + log-prob head ==============
        unsigned* peer_credit = mapa_ptr(&sh_credit, 0u);
        const float wout_i = W_out[i];
        const float bout   = b_out[0];
        float hacc0 = 0.f, hacc1 = 0.f;

        for (int t = 0; t < L; ++t) {
            // ALL threads gate on the LOCAL flag (steady state: 1 LDS, falls through)
            {
                const unsigned need = (unsigned)(t + 1);
                while (ld_acquire_cluster(&sh_flag) < need) { }
            }

            const int p = t & 1;
            const float* hr = &sh_h[p][0];
            const float h1v = sh_ring[t & (RING - 1)][s * H + i];

            uint64_t a00 = 0, a01 = 0, a10 = 0, a11 = 0;
            #pragma unroll
            for (int j = 0; j < 16; ++j) {
                const int o = 8 * j + 4 * s;
                const ulonglong2 h0 = *(const ulonglong2*)(hr + o);
                const ulonglong2 h1 = *(const ulonglong2*)(hr + H + o);
                a00 = ffma2(w[2*j],   h0.x, a00);
                a01 = ffma2(w[2*j+1], h0.y, a01);
                a10 = ffma2(w[2*j],   h1.x, a10);
                a11 = ffma2(w[2*j+1], h1.y, a11);
            }
            float p0 = hsum2(fadd2(a00, a01));
            float p1 = hsum2(fadd2(a10, a11));
            p0 += __shfl_xor_sync(0xffffffffu, p0, 1);
            p1 += __shfl_xor_sync(0xffffffffu, p1, 1);

            const float h2n = elu1(s ? p1 : p0) + h1v;
            sh_h[p ^ 1][s * H + i] = h2n;
            sh_prod[t & (RING - 1)][s * H + i] = h2n * wout_i;

            // amortized head: window [t-8, t-1], warp w -> slot t-8+w, both batches
            if ((t & 7) == 0 && t >= 8) {
                const int u = t - 8 + warp;
                #pragma unroll
                for (int b = 0; b < 2; ++b) {
                    const float4 v = *(const float4*)&sh_prod[u & (RING - 1)][b * H + lane * 4];
                    float sr = (v.x + v.y) + (v.z + v.w);
                    #pragma unroll
                    for (int off = 16; off; off >>= 1)
                        sr += __shfl_xor_sync(0xffffffffu, sr, off);
                    if (lane == 0) {
                        const float logit = sr + bout;
                        const int   xt    = sh_x[b * L + u];
                        const float m     = fmaxf(logit, 0.f);
                        const float lse   = m + __logf(__expf(-m) + __expf(logit - m));
                        const float gv    = 0.5f * ((xt ? logit : 0.f) - lse);
                        if (b == 0) hacc0 += gv; else hacc1 += gv;
                    }
                }
            }

            __syncthreads();   // h2 ping-pong + prod ring + (t covered by ring reads)
            // publish consumed count every 8 steps (incl. t = L-1)
            if ((t & 7) == 7 && tid == 0)
                st_release_cluster(peer_credit, (unsigned)(t + 1));
        }

        __syncthreads();
        // epilogue: last 8 slots [L-8, L-1]
        {
            const int u = L - 8 + warp;
            #pragma unroll
            for (int b = 0; b < 2; ++b) {
                const float4 v = *(const float4*)&sh_prod[u & (RING - 1)][b * H + lane * 4];
                float sr = (v.x + v.y) + (v.z + v.w);
                #pragma unroll
                for (int off = 16; off; off >>= 1)
                    sr += __shfl_xor_sync(0xffffffffu, sr, off);
                if (lane == 0) {
                    const float logit = sr + bout;
                    const int   xt    = sh_x[b * L + u];
                    const float m     = fmaxf(logit, 0.f);
                    const float lse   = m + __logf(__expf(-m) + __expf(logit - m));
                    const float gv    = 0.5f * ((xt ? logit : 0.f) - lse);
                    if (b == 0) hacc0 += gv; else hacc1 += gv;
                }
            }
        }
        if (lane == 0) { sh_acc[warp][0] = hacc0; sh_acc[warp][1] = hacc1; }
        __syncthreads();
        if (tid < 2) {
            float a = 0.f;
            #pragma unroll
            for (int wq = 0; wq < 8; ++wq) a += sh_acc[wq][tid];
            out[b0 + tid] = a;
        }
    }

    CLUSTER_SYNC();   // no CTA exits while the peer may still target its smem
}

extern "C" void kernel_launch(void* const* d_in, const int* in_sizes, int n_in,
                              void* d_out, int out_size)
{
    const int*   x     = (const int*)  d_in[0];
    const float* W_in  = (const float*)d_in[1];
    const float* W_c   = (const float*)d_in[2];
    const float* W_out = (const float*)d_in[3];
    const float* b_out = (const float*)d_in[4];

    rnn_cluster_kernel<<<BATCH, 256>>>(x, W_in, W_c, W_out, b_out, (float*)d_out);
}

// round 14
// speedup vs baseline: 1.0600x; 1.0600x over previous
#include <cuda_runtime.h>
#include <cstdint>

#define BATCH 256
#define L 4096
#define H 128

// ---------- packed f32x2 helpers (Blackwell sm_103a) ----------
__device__ __forceinline__ uint64_t pack2f(float a, float b) {
    uint64_t r; asm("mov.b64 %0, {%1, %2};" : "=l"(r) : "f"(a), "f"(b)); return r;
}
__device__ __forceinline__ float hsum2(uint64_t v) {
    float a, b; asm("mov.b64 {%0, %1}, %2;" : "=f"(a), "=f"(b) : "l"(v)); return a + b;
}
__device__ __forceinline__ uint64_t ffma2(uint64_t a, uint64_t b, uint64_t c) {
    uint64_t d; asm("fma.rn.f32x2 %0, %1, %2, %3;" : "=l"(d) : "l"(a), "l"(b), "l"(c)); return d;
}
__device__ __forceinline__ uint64_t fadd2(uint64_t a, uint64_t b) {
    uint64_t d; asm("add.rn.f32x2 %0, %1, %2;" : "=l"(d) : "l"(a), "l"(b)); return d;
}
__device__ __forceinline__ float elu1(float x) {
    return fmaxf(x, 0.f) + (__expf(fminf(x, 0.f)) - 1.f);
}

// One CTA = 2 batch elements, 256 threads.
// Warps 0-3: LAYER 1 — thread owns unit u = (warp&3)*32+lane, FULL 128-k dot for
//   both batches (weights: 64 packed regs, one layer only). Pure-broadcast LDS
//   (all lanes read the same h address), zero reduction shuffles.
// Warps 4-7: LAYER 2, lagged one step — at iteration n they compute h2(n-1)
//   from h2(n-2) and h1(n-1) (both published before the previous barrier), so
//   the two halves of an iteration are INDEPENDENT and one __syncthreads joins
//   balanced work. h1/h2 ping-pong by parity: h(m) lives in buffer m&1.
// Output head: prod ring (32 slots); every 8 iterations each warp reduces one
// slot u = n-10+warp (validity: written at iter u+1 <= n-2; overwrite at u+33).
__global__ void __launch_bounds__(256, 1)
rnn_scan_kernel(const int* __restrict__ x,
                const float* __restrict__ W_in,
                const float* __restrict__ W_c,
                const float* __restrict__ W_out,
                const float* __restrict__ b_out,
                float* __restrict__ out)
{
    __shared__ __align__(16) float sh_h1[2][2 * H];     // h1(m) in [m&1][b*H+unit]
    __shared__ __align__(16) float sh_h2[2][2 * H];     // h2(m) in [m&1][...]
    __shared__ __align__(16) float sh_r[3 * H];         // r for spin0/1, zero-prev
    __shared__ __align__(16) float sh_prod[32][2 * H];  // 32 KB head ring
    __shared__ uint8_t sh_x[2 * L];                     // 8 KB
    __shared__ float sh_acc[8][2];

    const int tid  = threadIdx.x;
    const int warp = tid >> 5;
    const int lane = tid & 31;
    const int unit = (warp & 3) * 32 + lane;   // hidden unit owned by this thread
    const bool isL1 = (warp < 4);
    const int b0   = blockIdx.x * 2;

    // ---- stage x; r table; zero initial states h1(-1), h2(-1) (buffers [1]) ----
    const int* xg = x + (size_t)b0 * L;
    #pragma unroll 4
    for (int idx = tid; idx < 2 * L; idx += 256) sh_x[idx] = (uint8_t)xg[idx];
    if (tid < 2 * H) sh_r[tid] = elu1(W_in[tid]);
    if (tid < H)     sh_r[2 * H + tid] = 0.f;
    if (tid < 2 * H) { sh_h1[1][tid] = 0.f; sh_h2[1][tid] = 0.f; }

    // ---- weights: this thread's layer, full column `unit` (64 packed regs) ----
    const float* Wl = W_c + (isL1 ? 0 : H * H);
    uint64_t w[64];
    #pragma unroll
    for (int j = 0; j < 64; ++j)
        w[j] = pack2f(Wl[(2 * j) * H + unit], Wl[(2 * j + 1) * H + unit]);

    const float wout_u = W_out[unit];
    const float bout   = b_out[0];
    float hacc0 = 0.f, hacc1 = 0.f;

    __syncthreads();

    // iterations n = 0..L: L1 computes h1(n) (n<L); L2 computes h2(n-1) (n>=1)
    for (int n = 0; n <= L; ++n) {
        // ===== amortized head: every 8 iters, warp w reduces slot u = n-10+w =====
        if ((n & 7) == 0 && n >= 8) {
            const int u = n - 10 + warp;
            if (u >= 0) {
                #pragma unroll
                for (int b = 0; b < 2; ++b) {
                    const float4 v = *(const float4*)&sh_prod[u & 31][b * H + lane * 4];
                    float sr = (v.x + v.y) + (v.z + v.w);
                    #pragma unroll
                    for (int off = 16; off; off >>= 1)
                        sr += __shfl_xor_sync(0xffffffffu, sr, off);
                    if (lane == 0) {
                        const float logit = sr + bout;
                        const int   xt    = sh_x[b * L + u];
                        const float m     = fmaxf(logit, 0.f);
                        const float lse   = m + __logf(__expf(-m) + __expf(logit - m));
                        const float gv    = 0.5f * ((xt ? logit : 0.f) - lse);
                        if (b == 0) hacc0 += gv; else hacc1 += gv;
                    }
                }
            }
        }

        if (isL1) {
            // ===== layer 1, step n: h1(n) = elu(h1(n-1) W0) + r(x(n-1)) =====
            if (n < L) {
                const float* hr = &sh_h1[(n + 1) & 1][0];   // h1(n-1)
                float*       hw = &sh_h1[n & 1][0];
                const int   pr0 = n ? (int)sh_x[n - 1]     : 2;
                const int   pr1 = n ? (int)sh_x[L + n - 1] : 2;
                const float rv0 = sh_r[pr0 * H + unit];
                const float rv1 = sh_r[pr1 * H + unit];

                uint64_t a0=0,a1=0,a2=0,a3=0,c0=0,c1=0,c2=0,c3=0;
                #pragma unroll
                for (int j = 0; j < 16; ++j) {
                    const int o = 8 * j;
                    const ulonglong2 u0 = *(const ulonglong2*)(hr + o);
                    const ulonglong2 u1 = *(const ulonglong2*)(hr + o + 4);
                    const ulonglong2 v0 = *(const ulonglong2*)(hr + H + o);
                    const ulonglong2 v1 = *(const ulonglong2*)(hr + H + o + 4);
                    a0 = ffma2(w[4*j],   u0.x, a0);
                    a1 = ffma2(w[4*j+1], u0.y, a1);
                    a2 = ffma2(w[4*j+2], u1.x, a2);
                    a3 = ffma2(w[4*j+3], u1.y, a3);
                    c0 = ffma2(w[4*j],   v0.x, c0);
                    c1 = ffma2(w[4*j+1], v0.y, c1);
                    c2 = ffma2(w[4*j+2], v1.x, c2);
                    c3 = ffma2(w[4*j+3], v1.y, c3);
                }
                const float d0 = hsum2(fadd2(fadd2(a0, a1), fadd2(a2, a3)));
                const float d1 = hsum2(fadd2(fadd2(c0, c1), fadd2(c2, c3)));
                hw[unit]     = elu1(d0) + rv0;
                hw[H + unit] = elu1(d1) + rv1;
            }
        } else {
            // ===== layer 2, step m = n-1: h2(m) = elu(h2(m-1) W1) + h1(m) =====
            if (n >= 1) {
                const int m = n - 1;
                const float* hr = &sh_h2[n & 1][0];          // h2(m-1) = h2(n-2)
                float*       hw = &sh_h2[(n + 1) & 1][0];    // h2(m)
                const float h1m0 = sh_h1[(n + 1) & 1][unit];       // h1(m)
                const float h1m1 = sh_h1[(n + 1) & 1][H + unit];

                uint64_t a0=0,a1=0,a2=0,a3=0,c0=0,c1=0,c2=0,c3=0;
                #pragma unroll
                for (int j = 0; j < 16; ++j) {
                    const int o = 8 * j;
                    const ulonglong2 u0 = *(const ulonglong2*)(hr + o);
                    const ulonglong2 u1 = *(const ulonglong2*)(hr + o + 4);
                    const ulonglong2 v0 = *(const ulonglong2*)(hr + H + o);
                    const ulonglong2 v1 = *(const ulonglong2*)(hr + H + o + 4);
                    a0 = ffma2(w[4*j],   u0.x, a0);
                    a1 = ffma2(w[4*j+1], u0.y, a1);
                    a2 = ffma2(w[4*j+2], u1.x, a2);
                    a3 = ffma2(w[4*j+3], u1.y, a3);
                    c0 = ffma2(w[4*j],   v0.x, c0);
                    c1 = ffma2(w[4*j+1], v0.y, c1);
                    c2 = ffma2(w[4*j+2], v1.x, c2);
                    c3 = ffma2(w[4*j+3], v1.y, c3);
                }
                const float d0 = hsum2(fadd2(fadd2(a0, a1), fadd2(a2, a3)));
                const float d1 = hsum2(fadd2(fadd2(c0, c1), fadd2(c2, c3)));
                const float h2n0 = elu1(d0) + h1m0;
                const float h2n1 = elu1(d1) + h1m1;
                hw[unit]     = h2n0;
                hw[H + unit] = h2n1;
                sh_prod[m & 31][unit]     = h2n0 * wout_u;
                sh_prod[m & 31][H + unit] = h2n1 * wout_u;
            }
        }

        __syncthreads();   // single barrier per iteration (joins independent halves)
    }

    // ===== epilogue: remaining head slots u = L-2, L-1 (warps 0,1) =====
    if (warp < 2) {
        const int u = L - 2 + warp;
        #pragma unroll
        for (int b = 0; b < 2; ++b) {
            const float4 v = *(const float4*)&sh_prod[u & 31][b * H + lane * 4];
            float sr = (v.x + v.y) + (v.z + v.w);
            #pragma unroll
            for (int off = 16; off; off >>= 1)
                sr += __shfl_xor_sync(0xffffffffu, sr, off);
            if (lane == 0) {
                const float logit = sr + bout;
                const int   xt    = sh_x[b * L + u];
                const float m     = fmaxf(logit, 0.f);
                const float lse   = m + __logf(__expf(-m) + __expf(logit - m));
                const float gv    = 0.5f * ((xt ? logit : 0.f) - lse);
                if (b == 0) hacc0 += gv; else hacc1 += gv;
            }
        }
    }

    if (lane == 0) { sh_acc[warp][0] = hacc0; sh_acc[warp][1] = hacc1; }
    __syncthreads();
    if (tid < 2) {
        float a = 0.f;
        #pragma unroll
        for (int wq = 0; wq < 8; ++wq) a += sh_acc[wq][tid];
        out[b0 + tid] = a;
    }
}

extern "C" void kernel_launch(void* const* d_in, const int* in_sizes, int n_in,
                              void* d_out, int out_size)
{
    const int*   x     = (const int*)  d_in[0];
    const float* W_in  = (const float*)d_in[1];
    const float* W_c   = (const float*)d_in[2];
    const float* W_out = (const float*)d_in[3];
    const float* b_out = (const float*)d_in[4];

    rnn_scan_kernel<<<BATCH / 2, 256>>>(x, W_in, W_c, W_out, b_out, (float*)d_out);
}